// round 9
// baseline (speedup 1.0000x reference)
#include <cuda_runtime.h>
#include <cuda_bf16.h>
#include <cstdint>

// Embedding gather via per-thread bulk-DMA: out[s,:] = weights[x[s],:]
// x: [8192] int32, weights: [49408, 768] fp32, out: [8192, 768] fp32
//
// Each CTA = 32 threads; thread t owns row s0+t end-to-end: its own 3072 B
// smem buffer, its own mbarrier, its own bulk_group. All 32 loads issue in
// parallel; waits and stores drain independently (no serialized driver loop).
// 256 CTAs x 32 rows = whole 24 MB problem queued in the async engine.

#define SEQ       8192
#define ROW_BYTES 3072
#define RPC       32                 // rows per CTA == threads per CTA
#define GRID      (SEQ / RPC)        // 256
#define SMEM_SZ   (RPC * ROW_BYTES + RPC * 8)   // 98560 B

__device__ __forceinline__ uint32_t smem_u32(const void* p) {
    uint32_t a;
    asm("{ .reg .u64 t; cvta.to.shared.u64 t, %1; cvt.u32.u64 %0, t; }"
        : "=r"(a) : "l"(p));
    return a;
}

__global__ void __launch_bounds__(RPC) embed_bulk_kernel(
    const int* __restrict__ x,
    const char* __restrict__ weights,
    char* __restrict__ out)
{
    extern __shared__ __align__(128) char smem[];
    // layout: [RPC][ROW_BYTES] buffers, then RPC mbarriers
    const int t  = threadIdx.x;
    const int s0 = blockIdx.x * RPC;

    const uint32_t buf  = smem_u32(smem) + t * ROW_BYTES;
    const uint32_t mbar = smem_u32(smem) + RPC * ROW_BYTES + t * 8;

    const int row = __ldg(&x[s0 + t]);

    // Each thread inits + uses only its own mbarrier.
    asm volatile("mbarrier.init.shared.b64 [%0], 1;" :: "r"(mbar) : "memory");
    asm volatile("fence.proxy.async.shared::cta;" ::: "memory");

    // Issue this thread's row load (32 independent 3072 B copies per CTA).
    asm volatile("mbarrier.arrive.expect_tx.shared.b64 _, [%0], %1;"
                 :: "r"(mbar), "r"((uint32_t)ROW_BYTES) : "memory");
    asm volatile(
        "cp.async.bulk.shared::cta.global.mbarrier::complete_tx::bytes "
        "[%0], [%1], %2, [%3];"
        :: "r"(buf),
           "l"(weights + (size_t)row * ROW_BYTES),
           "r"((uint32_t)ROW_BYTES),
           "r"(mbar)
        : "memory");

    // Wait own row, then bulk-store it out (per-thread bulk_group).
    asm volatile(
        "{\n\t"
        ".reg .pred P1;\n\t"
        "WL_%=:\n\t"
        "mbarrier.try_wait.parity.acquire.cta.shared::cta.b64 P1, [%0], 0, 0x989680;\n\t"
        "@P1 bra.uni WD_%=;\n\t"
        "bra.uni WL_%=;\n\t"
        "WD_%=:\n\t"
        "}" :: "r"(mbar) : "memory");
    asm volatile("fence.proxy.async.shared::cta;" ::: "memory");
    asm volatile(
        "cp.async.bulk.global.shared::cta.bulk_group [%0], [%1], %2;"
        :: "l"(out + (size_t)(s0 + t) * ROW_BYTES),
           "r"(buf),
           "r"((uint32_t)ROW_BYTES)
        : "memory");
    asm volatile("cp.async.bulk.commit_group;" ::: "memory");
    asm volatile("cp.async.bulk.wait_group 0;" ::: "memory");
}

extern "C" void kernel_launch(void* const* d_in, const int* in_sizes, int n_in,
                              void* d_out, int out_size) {
    const int*  x = (const int*)d_in[0];
    const char* w = (const char*)d_in[1];
    char*       o = (char*)d_out;
    static bool attr_set = false;
    if (!attr_set) {
        cudaFuncSetAttribute(embed_bulk_kernel,
                             cudaFuncAttributeMaxDynamicSharedMemorySize, SMEM_SZ);
        attr_set = true;
    }
    embed_bulk_kernel<<<GRID, RPC, SMEM_SZ>>>(x, w, o);
}